// round 4
// baseline (speedup 1.0000x reference)
#include <cuda_runtime.h>
#include <cuda_fp16.h>

#define BB 8
#define LL 512
#define DD 128
#define INV_SCALE 0.08838834764831843f   // 1/sqrt(128)

typedef unsigned long long ull;

// ---- scratch (no cudaMalloc allowed) ----
__device__ float g_Q[BB*LL*DD];
__device__ float g_K[BB*LL*DD];
__device__ float g_V[BB*LL*DD];

__device__ __forceinline__ __half2 tanh_h2(__half2 x) {
    unsigned xi = *(unsigned*)&x, yi;
    asm("tanh.approx.f16x2 %0, %1;" : "=r"(yi) : "r"(xi));
    return *(__half2*)&yi;
}
__device__ __forceinline__ ull ffma2(ull a, ull b, ull c) {
    ull d;
    asm("fma.rn.f32x2 %0, %1, %2, %3;" : "=l"(d) : "l"(a), "l"(b), "l"(c));
    return d;
}
__device__ __forceinline__ ull pack2(float x) {
    ull d;
    asm("mov.b64 %0, {%1, %1};" : "=l"(d) : "f"(x));
    return d;
}
__device__ __forceinline__ float2 unpack2(ull v) {
    float2 r;
    asm("mov.b64 {%0, %1}, %2;" : "=f"(r.x), "=f"(r.y) : "l"(v));
    return r;
}

// =====================================================================
// Projection: out = X @ W.T + b  (FFMA2 inner product, packed col pairs)
// grid 96 (mat = bx>>5, 128-row tile = bx&31), 256 threads
// smem: Xs[128][129] + Wt[128][130] (Wt[d][c], even pitch for 8B align)
// =====================================================================
#define XS_PITCH 129
#define WT_PITCH 130
#define PROJ_SMEM_FLOATS (128*XS_PITCH + 128*WT_PITCH)

__global__ void __launch_bounds__(256) proj_kernel(
    const float* __restrict__ Xq, const float* __restrict__ Xk, const float* __restrict__ Xv,
    const float* __restrict__ Wq, const float* __restrict__ bq,
    const float* __restrict__ Wk, const float* __restrict__ bk,
    const float* __restrict__ Wv, const float* __restrict__ bv)
{
    extern __shared__ float sm[];
    float* Xs = sm;                    // [128][129]
    float* Wt = sm + 128*XS_PITCH;     // [128][130]  Wt[d][c]
    __shared__ float bs[DD];

    int bx  = blockIdx.x;
    int mat = bx >> 5;
    int rt  = bx & 31;
    const float *X, *W, *bias;
    float* out;
    if (mat == 0)      { X = Xq; W = Wq; bias = bq; out = g_Q; }
    else if (mat == 1) { X = Xk; W = Wk; bias = bk; out = g_K; }
    else               { X = Xv; W = Wv; bias = bv; out = g_V; }

    int tid = threadIdx.x;
    const float4* Xg = (const float4*)(X + rt*128*DD);
    const float4* Wg = (const float4*)W;
    #pragma unroll
    for (int it = 0; it < 16; ++it) {
        int idx = it*256 + tid;           // 0..4095 float4 groups
        int d4  = idx & 31;               // d = 4*d4
        int r   = idx >> 5;               // row (or out-col c for W)
        float4 xv = Xg[idx];
        float* xd = Xs + r*XS_PITCH + 4*d4;
        xd[0] = xv.x; xd[1] = xv.y; xd[2] = xv.z; xd[3] = xv.w;
        float4 wv = Wg[idx];
        Wt[(4*d4+0)*WT_PITCH + r] = wv.x;
        Wt[(4*d4+1)*WT_PITCH + r] = wv.y;
        Wt[(4*d4+2)*WT_PITCH + r] = wv.z;
        Wt[(4*d4+3)*WT_PITCH + r] = wv.w;
    }
    if (tid < DD) bs[tid] = bias[tid];
    __syncthreads();

    int tr = tid >> 4;     // 0..15 (8-row group)
    int tc = tid & 15;     // 0..15 (8-col group)
    const float* xb = Xs + (tr*8)*XS_PITCH;
    const float* wb = Wt + tc*8;

    ull acc[8][4];
    #pragma unroll
    for (int i = 0; i < 8; ++i)
        #pragma unroll
        for (int j = 0; j < 4; ++j) acc[i][j] = 0ull;

    #pragma unroll 4
    for (int d = 0; d < DD; ++d) {
        float xs[8]; ull xp[8]; ull wp[4];
        #pragma unroll
        for (int i = 0; i < 8; ++i) xs[i] = xb[i*XS_PITCH + d];
        #pragma unroll
        for (int j = 0; j < 4; ++j) wp[j] = *(const ull*)(wb + d*WT_PITCH + 2*j);
        #pragma unroll
        for (int i = 0; i < 8; ++i) xp[i] = pack2(xs[i]);
        #pragma unroll
        for (int i = 0; i < 8; ++i)
            #pragma unroll
            for (int j = 0; j < 4; ++j) acc[i][j] = ffma2(xp[i], wp[j], acc[i][j]);
    }

    int rbase = rt*128 + tr*8;
    #pragma unroll
    for (int i = 0; i < 8; ++i) {
        float* orow = out + (rbase + i)*DD + tc*8;
        #pragma unroll
        for (int j = 0; j < 4; ++j) {
            float2 v = unpack2(acc[i][j]);
            orow[2*j+0] = v.x + bs[tc*8 + 2*j+0];
            orow[2*j+1] = v.y + bs[tc*8 + 2*j+1];
        }
    }
}

// =====================================================================
// Attention. Per block: one batch b, one 32-row q tile. 512 threads.
// Phase 1: scores via tanh.approx.f16x2 + HFMA2 chunked accumulation
// Phase 2: row softmax (b_all softmax-invariant -> dropped)
// Phase 3: O = P @ V with fma.rn.f32x2 (V packed in k-adjacent pairs)
// smem (floats): S[32][512] | KV (Kh[128][33]h2 / Vp[32][128]ull) |
//                Qh[32][128]h2 | wh[128]h2 | rinv[32]
// =====================================================================
#define SM_S    0
#define SM_KV   (32*512)                 // 16384 (even -> 8B aligned)
#define SM_QH   (SM_KV + 32*128*2)       // Vp needs 8192 float-slots
#define SM_WH   (SM_QH + 32*128)
#define SM_RINV (SM_WH + 128)
#define ATTN_SMEM_FLOATS (SM_RINV + 32)

__global__ void __launch_bounds__(512) attn_kernel(
    const float* __restrict__ wdel, const float* __restrict__ wsig,
    const float* __restrict__ wthe, float* __restrict__ out)
{
    extern __shared__ float sm[];
    float*   S    = sm + SM_S;
    __half2* Kh   = (__half2*)(sm + SM_KV);    // [128][33], pair (k, k+32)
    __half2* Qh   = (__half2*)(sm + SM_QH);    // [32][128], replicated
    __half2* wh   = (__half2*)(sm + SM_WH);    // [128], replicated
    float*   rinv = sm + SM_RINV;

    int tid  = threadIdx.x;
    int w    = tid >> 5;
    int lane = tid & 31;
    int b    = blockIdx.x >> 4;
    int qt   = blockIdx.x & 15;
    int qbase = qt * 32;

    const float* Qg = g_Q + (b*LL + qbase)*DD;
    const float* Kg = g_K + b*LL*DD;
    const float* Vg = g_V + b*LL*DD;

    // stage Qh (replicated half2) + combined weight vector (replicated half2)
    #pragma unroll
    for (int it = 0; it < 8; ++it) {
        int i = it*512 + tid;              // 0..4095
        float f = Qg[i];
        Qh[i] = __floats2half2_rn(f, f);
    }
    if (tid < DD) {
        float wv = INV_SCALE + wdel[tid] + wsig[tid] + wthe[tid];
        wh[tid] = __floats2half2_rn(wv, wv);
    }

    // ---------------- Phase 1: scores (MUFU f16x2) ----------------
    int q0 = 2*w, q1 = q0 + 1;
    const __half2* Qr0 = Qh + q0*128;
    const __half2* Qr1 = Qh + q1*128;
    for (int kt = 0; kt < 8; ++kt) {
        __syncthreads();   // KV free (covers Qh/wh staging on first iter)
        // stage K tile as pairs: Kh[d][k] = (K[kt*64+k][d], K[kt*64+32+k][d])
        const float4* Ka = (const float4*)(Kg + kt*64*DD);
        #pragma unroll
        for (int it = 0; it < 2; ++it) {
            int idx = it*512 + tid;        // 0..1023
            int k = idx >> 5, d4 = idx & 31;
            float4 a = Ka[k*32 + d4];
            float4 bb = Ka[(k+32)*32 + d4];
            Kh[(4*d4+0)*33 + k] = __floats2half2_rn(a.x, bb.x);
            Kh[(4*d4+1)*33 + k] = __floats2half2_rn(a.y, bb.y);
            Kh[(4*d4+2)*33 + k] = __floats2half2_rn(a.z, bb.z);
            Kh[(4*d4+3)*33 + k] = __floats2half2_rn(a.w, bb.w);
        }
        __syncthreads();

        float a00 = 0.f, a01 = 0.f, a10 = 0.f, a11 = 0.f;
        #pragma unroll 2
        for (int dc = 0; dc < DD; dc += 8) {
            __half2 c0 = __floats2half2_rn(0.f, 0.f);
            __half2 c1 = c0;
            #pragma unroll
            for (int dd = 0; dd < 8; ++dd) {
                int d = dc + dd;
                __half2 kv = Kh[d*33 + lane];
                __half2 w2 = wh[d];
                __half2 t0 = tanh_h2(__hadd2(Qr0[d], kv));
                __half2 t1 = tanh_h2(__hadd2(Qr1[d], kv));
                c0 = __hfma2(t0, w2, c0);
                c1 = __hfma2(t1, w2, c1);
            }
            float2 f0 = __half22float2(c0);
            float2 f1 = __half22float2(c1);
            a00 += f0.x; a01 += f0.y; a10 += f1.x; a11 += f1.y;
        }
        S[q0*512 + kt*64 + lane]      = a00;
        S[q0*512 + kt*64 + 32 + lane] = a01;
        S[q1*512 + kt*64 + lane]      = a10;
        S[q1*512 + kt*64 + 32 + lane] = a11;
    }
    // each warp softmaxes the rows it wrote itself -> no sync needed here

    // ---------------- Phase 2: softmax ----------------
    #pragma unroll
    for (int rr = 0; rr < 2; ++rr) {
        int q = 2*w + rr;
        float* Srow = S + q*512;
        float v[16];
        float m = -1e30f;
        #pragma unroll
        for (int i = 0; i < 16; ++i) { v[i] = Srow[i*32 + lane]; m = fmaxf(m, v[i]); }
        #pragma unroll
        for (int s = 16; s > 0; s >>= 1) m = fmaxf(m, __shfl_xor_sync(0xffffffffu, m, s));
        float sum = 0.f;
        #pragma unroll
        for (int i = 0; i < 16; ++i) {
            float e = __expf(v[i] - m);
            Srow[i*32 + lane] = e;
            sum += e;
        }
        #pragma unroll
        for (int s = 16; s > 0; s >>= 1) sum += __shfl_xor_sync(0xffffffffu, sum, s);
        if (lane == 0) rinv[q] = 1.0f / sum;
    }

    // ---------------- Phase 3: O = P @ V (FFMA2) ----------------
    // warp -> 4 rows (w&7), 64-col half (w>>3); lane owns d = dofA and dofA+32
    // acc[i][x] packs (even-k partial, odd-k partial); horizontal add at end
    int r0  = (w & 7) * 4;
    int dh  = w >> 3;
    int dA  = dh*64 + lane;          // first d
    ull acc[4][2] = {{0,0},{0,0},{0,0},{0,0}};
    const ull* Vp = (const ull*)(sm + SM_KV);   // [32][128] : Vp[k2][d]

    for (int kt = 0; kt < 8; ++kt) {
        __syncthreads();   // previous tile consumed (also fences rinv on kt=0)
        // stage V pairs: Vp[k2][d] = (V[2k2][d], V[2k2+1][d])
        const float4* Va = (const float4*)(Vg + kt*64*DD);
        float2* Vp2 = (float2*)(sm + SM_KV);
        #pragma unroll
        for (int it = 0; it < 2; ++it) {
            int idx = it*512 + tid;        // 0..1023
            int k2 = idx >> 5, d4 = idx & 31;
            float4 a = Va[(2*k2)*32 + d4];
            float4 bb = Va[(2*k2+1)*32 + d4];
            Vp2[k2*128 + 4*d4 + 0] = make_float2(a.x, bb.x);
            Vp2[k2*128 + 4*d4 + 1] = make_float2(a.y, bb.y);
            Vp2[k2*128 + 4*d4 + 2] = make_float2(a.z, bb.z);
            Vp2[k2*128 + 4*d4 + 3] = make_float2(a.w, bb.w);
        }
        __syncthreads();

        const float* Sb = S + kt*64;
        #pragma unroll 4
        for (int k2 = 0; k2 < 32; ++k2) {
            ull p0 = *(const ull*)(Sb + (r0+0)*512 + 2*k2);
            ull p1 = *(const ull*)(Sb + (r0+1)*512 + 2*k2);
            ull p2 = *(const ull*)(Sb + (r0+2)*512 + 2*k2);
            ull p3 = *(const ull*)(Sb + (r0+3)*512 + 2*k2);
            ull v0 = Vp[k2*128 + dA];
            ull v1 = Vp[k2*128 + dA + 32];
            acc[0][0] = ffma2(p0, v0, acc[0][0]);  acc[0][1] = ffma2(p0, v1, acc[0][1]);
            acc[1][0] = ffma2(p1, v0, acc[1][0]);  acc[1][1] = ffma2(p1, v1, acc[1][1]);
            acc[2][0] = ffma2(p2, v0, acc[2][0]);  acc[2][1] = ffma2(p2, v1, acc[2][1]);
            acc[3][0] = ffma2(p3, v0, acc[3][0]);  acc[3][1] = ffma2(p3, v1, acc[3][1]);
        }
    }

    #pragma unroll
    for (int i = 0; i < 4; ++i) {
        float inv = rinv[r0 + i];
        float2 eo = unpack2(acc[i][0]);
        float2 e1 = unpack2(acc[i][1]);
        float* orow = out + (size_t)(b*LL + qbase + r0 + i)*DD;
        orow[dA]      = (eo.x + eo.y) * inv;
        orow[dA + 32] = (e1.x + e1.y) * inv;
    }
}

// =====================================================================
extern "C" void kernel_launch(void* const* d_in, const int* in_sizes, int n_in,
                              void* d_out, int out_size)
{
    const float* query = (const float*)d_in[0];
    const float* key   = (const float*)d_in[1];
    const float* value = (const float*)d_in[2];
    const float* Wq    = (const float*)d_in[3];
    const float* bq    = (const float*)d_in[4];
    const float* Wk    = (const float*)d_in[5];
    const float* bk    = (const float*)d_in[6];
    const float* Wv    = (const float*)d_in[7];
    const float* bv    = (const float*)d_in[8];
    const float* wdel  = (const float*)d_in[9];
    const float* wsig  = (const float*)d_in[11];
    const float* wthe  = (const float*)d_in[13];
    float* out = (float*)d_out;

    const int PROJ_SMEM = PROJ_SMEM_FLOATS * (int)sizeof(float);
    const int ATTN_SMEM = ATTN_SMEM_FLOATS * (int)sizeof(float);

    cudaFuncSetAttribute(proj_kernel, cudaFuncAttributeMaxDynamicSharedMemorySize, PROJ_SMEM);
    cudaFuncSetAttribute(attn_kernel, cudaFuncAttributeMaxDynamicSharedMemorySize, ATTN_SMEM);

    proj_kernel<<<96, 256, PROJ_SMEM>>>(query, key, value, Wq, bq, Wk, bk, Wv, bv);
    attn_kernel<<<BB*16, 512, ATTN_SMEM>>>(wdel, wsig, wthe, out);
}